// round 9
// baseline (speedup 1.0000x reference)
#include <cuda_runtime.h>
#include <stdint.h>
#include <math.h>

#define NCAND  1600
#define NITER  100
#define NZ     16
#define NB     65536                // 2^16 bins
#define FRAC   7                    // sub-bin bits; NB<<FRAC = 2^23
#define NCHUNK 128
#define CHUNK  (NB / NCHUNK)        // 512
#define MMGRID 512

#define MAGICF 8388608.0f           // 2^23
#define HIF    16777215.0f          // 2^24 - 1
#define OVF    16777216.0f          // 2^24

typedef unsigned long long u64;
typedef long long          s64;
typedef unsigned           u32;

// ---------------- device scratch ----------------
__device__ float g_bmin[MMGRID], g_bmax[MMGRID];
__device__ float g_xminf, g_xmaxf, g_C1, g_C2;
__device__ float g_sc[NCAND], g_ql[NCAND];
__device__ float g_newmin[NCAND], g_newmax[NCAND];
__device__ u64   g_hist[NB];        // (count << 32) | sum_of_7bit_offsets
__device__ u32   g_pc[NB + 1];      // chunk-relative exclusive prefix counts
__device__ u64   g_ps[NB + 1];      // chunk-relative exclusive prefix units
__device__ u32   g_ccnt[NCHUNK];
__device__ u64   g_csum[NCHUNK];

// ---------------- pass A: per-block min/max + clear histogram ----------------
__global__ void minmax_clear_kernel(const float4* __restrict__ x4, int n4) {
    int stride = gridDim.x * blockDim.x;
    int tid0 = blockIdx.x * blockDim.x + threadIdx.x;

    for (int i = tid0; i < NB; i += stride) g_hist[i] = 0ull;   // 512 KB clear

    float lmin = 3.4e38f, lmax = -3.4e38f;
    for (int i = tid0; i < n4; i += stride) {
        float4 v = __ldg(&x4[i]);
        lmin = fminf(lmin, fminf(fminf(v.x, v.y), fminf(v.z, v.w)));
        lmax = fmaxf(lmax, fmaxf(fmaxf(v.x, v.y), fmaxf(v.z, v.w)));
    }
    #pragma unroll
    for (int o = 16; o; o >>= 1) {
        lmin = fminf(lmin, __shfl_xor_sync(0xffffffffu, lmin, o));
        lmax = fmaxf(lmax, __shfl_xor_sync(0xffffffffu, lmax, o));
    }
    __shared__ float smin[8], smax[8];
    int w = threadIdx.x >> 5;
    if ((threadIdx.x & 31) == 0) { smin[w] = lmin; smax[w] = lmax; }
    __syncthreads();
    if (threadIdx.x == 0) {
        for (int i = 1; i < (int)(blockDim.x >> 5); i++) {
            lmin = fminf(lmin, smin[i]);
            lmax = fmaxf(lmax, smax[i]);
        }
        g_bmin[blockIdx.x] = lmin;
        g_bmax[blockIdx.x] = lmax;
    }
}

// ---------------- pass B: finish min/max + bin constants + cand params --------
__global__ void __launch_bounds__(512) cand_kernel() {
    __shared__ float smn[512], smx[512];
    int t = threadIdx.x;
    smn[t] = g_bmin[t];              // MMGRID == 512
    smx[t] = g_bmax[t];
    __syncthreads();
    for (int off = 256; off; off >>= 1) {
        if (t < off) {
            smn[t] = fminf(smn[t], smn[t + off]);
            smx[t] = fmaxf(smx[t], smx[t + off]);
        }
        __syncthreads();
    }
    const float x_min = smn[0];
    const float x_max = smx[0];
    const float xrange = x_max - x_min;
    if (t == 0) {
        float C1 = MAGICF / xrange;
        g_xminf = x_min;
        g_xmaxf = x_max;
        g_C1 = C1;
        g_C2 = MAGICF - x_min * C1;
    }
    const float EPS = 1.1920929e-7f;  // np.finfo(float32).eps
    for (int c = t; c < NCAND; c += 512) {
        int i = c / NZ + 1;
        int z = c % NZ;
        float fi = (float)i, fz = (float)z;
        float tmp_max   = xrange / 100.0f * fi;
        float tmp_delta = tmp_max / 15.0f;
        float new_min = fmaxf(-fz * tmp_delta, x_min);
        float new_max = fminf(tmp_max - fz * tmp_delta, x_max);
        float min_neg = fminf(new_min, 0.0f);
        float max_pos = fmaxf(new_max, 0.0f);
        float scale = fmaxf((max_pos - min_neg) / 15.0f, EPS);
        float zp = fminf(fmaxf(0.0f - rintf(min_neg / scale), 0.0f), 15.0f);
        g_sc[c] = scale;
        g_ql[c] = -zp;
        g_newmin[c] = new_min;
        g_newmax[c] = new_max;
    }
}

// ---------------- pass C: histogram, magic binning, ONE u64 atomic ------------
// t = fma(x, C1, C2) in [2^23, 2^24): mantissa bits == 23-bit position.
// bin = q>>7, sub-bin offset q&127 accumulated exactly in low word.
__global__ void hist_kernel(const float4* __restrict__ x4, int n4) {
    const float C1 = g_C1;
    const float C2 = g_C2;
    int stride = gridDim.x * blockDim.x;
    #pragma unroll 2
    for (int i = blockIdx.x * blockDim.x + threadIdx.x; i < n4; i += stride) {
        float4 v = __ldg(&x4[i]);
        float f[4] = {v.x, v.y, v.z, v.w};
        #pragma unroll
        for (int k = 0; k < 4; k++) {
            float t = fmaf(f[k], C1, C2);
            t = fminf(fmaxf(t, MAGICF), HIF);
            u32 q = __float_as_uint(t) - 0x4B000000u;
            atomicAdd(&g_hist[q >> FRAC],
                      (1ull << 32) + (u64)(q & ((1u << FRAC) - 1u)));
        }
    }
}

// ---------------- pass D: per-chunk scan (block b <-> chunk b) ----------------
__global__ void __launch_bounds__(CHUNK) scan_kernel() {
    __shared__ u32 sc[CHUNK];
    __shared__ u64 ss[CHUNK];
    int b = blockIdx.x, t = threadIdx.x;
    int i = b * CHUNK + t;
    u64 p = g_hist[i];
    u32 v = (u32)(p >> 32);
    u64 w = ((u64)v * (u64)i << FRAC) + (p & 0xFFFFFFFFull);
    sc[t] = v; ss[t] = w; __syncthreads();
    for (int off = 1; off < CHUNK; off <<= 1) {
        u32 a = 0; u64 a2 = 0;
        if (t >= off) { a = sc[t - off]; a2 = ss[t - off]; }
        __syncthreads();
        sc[t] += a; ss[t] += a2;
        __syncthreads();
    }
    g_pc[i] = sc[t] - v;                 // chunk-relative exclusive
    g_ps[i] = ss[t] - w;
    if (t == CHUNK - 1) {
        g_ccnt[b] = sc[t];
        g_csum[b] = ss[t];
        if (b == NCHUNK - 1) { g_pc[NB] = 0u; g_ps[NB] = 0ull; }
    }
}

// ---------------- pass E: chunk prefix + scores + reference-exact select ------
__global__ void __launch_bounds__(1024) finish_kernel(float* __restrict__ out,
                                                      int ntot) {
    __shared__ u32    s_cc[NCHUNK];
    __shared__ u64    s_cs[NCHUNK];
    __shared__ u32    s_cpref[NCHUNK + 1];
    __shared__ u64    s_spref[NCHUNK + 1];
    __shared__ double s_score[NCAND];
    __shared__ double sm_i[NITER];
    __shared__ int    j_i[NITER];
    int t = threadIdx.x;

    if (t < NCHUNK) { s_cc[t] = g_ccnt[t]; s_cs[t] = g_csum[t]; }
    __syncthreads();
    if (t <= NCHUNK) {
        u32 c = 0; u64 s = 0;
        for (int j = 0; j < t; j++) { c += s_cc[j]; s += s_cs[j]; }
        s_cpref[t] = c; s_spref[t] = s;
    }
    __syncthreads();

    const float x_min = g_xminf;
    const float C1 = g_C1;
    const float C2 = g_C2;
    const float xrange = g_xmaxf - x_min;
    const double xmind = (double)x_min;
    const double UPQ = (double)xrange / (double)(NB << FRAC);  // x per unit

    for (int c = t; c < NCAND; c += 1024) {
        float scale = g_sc[c];
        float ql    = g_ql[c];

        int e[NZ + 1];
        e[0] = 0; e[NZ] = NB;
        #pragma unroll
        for (int m = 0; m < NZ - 1; m++) {
            float tr = fmaf((ql + (float)m + 0.5f) * scale, C1, C2);
            int ei;
            if (!(tr > MAGICF))      ei = 0;
            else if (tr >= OVF)      ei = NB;
            else ei = (int)((__float_as_uint(tr) - 0x4B000000u) >> FRAC);
            e[m + 1] = ei;
        }
        #pragma unroll
        for (int m = 1; m < NZ; m++) if (e[m] < e[m - 1]) e[m] = e[m - 1];

        double num = 0.0;
        #pragma unroll
        for (int m = 0; m < NZ; m++) {
            int e0 = e[m], e1 = e[m + 1];
            u32 pc0 = s_cpref[e0 >> 9] + g_pc[e0];
            u32 pc1 = s_cpref[e1 >> 9] + g_pc[e1];
            u64 ps0 = s_spref[e0 >> 9] + g_ps[e0];
            u64 ps1 = s_spref[e1 >> 9] + g_ps[e1];
            double Nm = (double)(pc1 - pc0);
            double S1 = (double)(s64)(ps1 - ps0) * UPQ + Nm * xmind;
            float a = (ql + (float)m) * scale;
            double ad = (double)a;
            num += ad * ad * Nm - 2.0 * ad * S1;
        }
        s_score[c] = num / (double)ntot;     // Σx² omitted: constant offset
    }
    __syncthreads();

    if (t < NITER) {
        int j = 0;
        double sm = s_score[t * NZ];
        #pragma unroll
        for (int z = 1; z < NZ; z++) {
            double s = s_score[t * NZ + z];
            if (s < sm) { sm = s; j = z; }   // first-occurrence argmin
        }
        sm_i[t] = sm; j_i[t] = j;
    }
    __syncthreads();
    if (t == 0) {
        double best = 1e30;
        float bmin = g_xminf, bmax = g_xmaxf;
        for (int i = 0; i < NITER; i++) {
            if (sm_i[i] < best) {            // strict <, like reference
                best = sm_i[i];
                bmin = g_newmin[i * NZ + j_i[i]];
                bmax = g_newmax[i * NZ + j_i[i]];
            }
        }
        out[0] = bmin;
        out[1] = bmax;
    }
}

extern "C" void kernel_launch(void* const* d_in, const int* in_sizes, int n_in,
                              void* d_out, int out_size) {
    const float* x = (const float*)d_in[0];
    int n = in_sizes[0];
    int n4 = n / 4;

    minmax_clear_kernel<<<MMGRID, 256>>>((const float4*)x, n4);
    cand_kernel<<<1, 512>>>();
    hist_kernel<<<2048, 256>>>((const float4*)x, n4);
    scan_kernel<<<NCHUNK, CHUNK>>>();
    finish_kernel<<<1, 1024>>>((float*)d_out, n);
}